// round 15
// baseline (speedup 1.0000x reference)
#include <cuda_runtime.h>
#include <cuda_bf16.h>
#include <mma.h>
#include <math.h>
#include <stdint.h>

using namespace nvcuda;

#define T 1024
#define D 768
#define H 12
#define FF 3072
#define V 8192
#define HD 64
#define NFF (H*FF)   // 36864

typedef __nv_bfloat16 bf16;

// ---------------- scratch (device globals; no allocation allowed) ----------
__device__ bf16  g_xnorm_bf[T*D];
__device__ float g_qk[T*2*D];
__device__ bf16  g_qkw_bf[2*D*D];
__device__ bf16  g_fcw_bf[(size_t)NFF*D];       // 56.6 MB (L2-resident)
__device__ bf16  g_projw_bf[H*HD*FF];
__device__ bf16  g_dict_bf[H*V*HD];
__device__ bf16  g_x2_bf[T*D];
__device__ bf16  g_h_bf[(size_t)T*NFF];         // 75.5 MB
__device__ float g_v[H*T*HD];
__device__ float g_y[H*T*HD];
__device__ float g_proj[H*T*HD];
__device__ float g_xhat[H*T*HD];
__device__ bf16  g_xhat_bf[H*T*HD];
__device__ bf16  g_probs_bf[(size_t)H*T*V];     // 201 MB
__device__ float g_recon[H*T*HD];

__constant__ float c_slopes[H] = {
    0.5f, 0.25f, 0.125f, 0.0625f, 0.03125f, 0.015625f, 0.0078125f, 0.00390625f,
    0.70710678118654752f, 0.5f, 0.35355339059327376f, 0.25f
};

__device__ __forceinline__ float gelu_exact(float x) {
    return 0.5f * x * (1.0f + erff(x * 0.70710678118654752f));
}

__device__ __forceinline__ uint32_t smem_u32(const void* p) {
    return (uint32_t)__cvta_generic_to_shared(p);
}
#define CP_ASYNC16(dst_u32, src) \
    asm volatile("cp.async.cg.shared.global [%0], [%1], 16;\n" :: "r"(dst_u32), "l"(src))
#define CP_COMMIT() asm volatile("cp.async.commit_group;\n")
#define CP_WAIT1()  asm volatile("cp.async.wait_group 1;\n")

template<typename OutT> __device__ __forceinline__ OutT to_out(float v);
template<> __device__ __forceinline__ float to_out<float>(float v) { return v; }
template<> __device__ __forceinline__ bf16  to_out<bf16>(float v)  { return __float2bfloat16(v); }

// ---------------- fp32 -> bf16 bulk convert (8 elems / thread) ------------
__global__ void f2bf_kernel(const float4* __restrict__ in, uint4* __restrict__ out, int n8) {
    int i = blockIdx.x * 256 + threadIdx.x;
    if (i < n8) {
        float4 a = in[2*i], b = in[2*i+1];
        __nv_bfloat162 p0 = __float22bfloat162_rn(make_float2(a.x, a.y));
        __nv_bfloat162 p1 = __float22bfloat162_rn(make_float2(a.z, a.w));
        __nv_bfloat162 p2 = __float22bfloat162_rn(make_float2(b.x, b.y));
        __nv_bfloat162 p3 = __float22bfloat162_rn(make_float2(b.z, b.w));
        uint4 o;
        o.x = *(uint32_t*)&p0; o.y = *(uint32_t*)&p1;
        o.z = *(uint32_t*)&p2; o.w = *(uint32_t*)&p3;
        out[i] = o;
    }
}

// ---------------- zero fp32 buffer ----------------------------------------
__global__ void zero_kernel(float4* __restrict__ p, int n4) {
    int i = blockIdx.x * 256 + threadIdx.x;
    if (i < n4) p[i] = make_float4(0.f, 0.f, 0.f, 0.f);
}

// ---------------- LayerNorm over 768: out_bf = LN(a+b)*w + bb -------------
__global__ void ln768_kernel(const float* __restrict__ a, const float* __restrict__ b,
                             const float* __restrict__ w, const float* __restrict__ bb,
                             bf16* __restrict__ out) {
    int t = blockIdx.x;
    int tid = threadIdx.x;                  // 256
    __shared__ float x[D];
    __shared__ float red[256];
    for (int i = tid; i < D; i += 256) x[i] = a[t*D + i] + b[t*D + i];
    __syncthreads();
    float s = 0.f;
    for (int i = tid; i < D; i += 256) s += x[i];
    red[tid] = s; __syncthreads();
    for (int st = 128; st > 0; st >>= 1) { if (tid < st) red[tid] += red[tid+st]; __syncthreads(); }
    float mu = red[0] / D;
    __syncthreads();
    float v = 0.f;
    for (int i = tid; i < D; i += 256) { float d = x[i] - mu; v += d*d; }
    red[tid] = v; __syncthreads();
    for (int st = 128; st > 0; st >>= 1) { if (tid < st) red[tid] += red[tid+st]; __syncthreads(); }
    float rs = rsqrtf(red[0]/D + 1e-5f);
    __syncthreads();
    for (int i = tid; i < D; i += 256)
        out[t*D + i] = __float2bfloat16((x[i] - mu) * rs * w[i] + bb[i]);
}

// ============================================================================
// bf16 GEMM, 3-stage cp.async pipeline (dynamic smem), fp32 accumulate.
//   BTRANS=0: C = A[M,K] * B[N,K]^T ; BTRANS=1: C = A[M,K] * B[K,N]
//   ACT=1: exact GELU. SPLITK>1: atomicAdd into pre-zeroed fp32 C.
// ============================================================================
template<int BM, int BN, int WM, int WN, int BTRANS, int ACT, typename OutT, int SPLITK = 1>
__global__ void __launch_bounds__(256) bgemm(
    const bf16* __restrict__ A, int lda, long long sA,
    const bf16* __restrict__ B, int ldb, long long sB,
    const float* __restrict__ bias, long long sBias,
    OutT* __restrict__ C, int ldc, long long sC, int K)
{
    constexpr int BK = 32;
    constexpr int BKP = 40;
    constexpr int BNP = BN + 8;
    constexpr int AS_ELEMS = BM * BKP;
    constexpr int BS_ELEMS = BTRANS ? BK * BNP : BN * BKP;
    extern __shared__ char smraw[];
    bf16* AsBase = (bf16*)smraw;
    bf16* BsBase = (bf16*)(smraw + 3 * AS_ELEMS * 2);

    int z = blockIdx.z;
    A += (long long)z * sA; B += (long long)z * sB; C += (long long)z * sC;
    int nTiles = gridDim.x / SPLITK;
    int ntile = blockIdx.x % nTiles;
    int split = blockIdx.x / nTiles;
    int bm = blockIdx.y * BM, bn = ntile * BN;
    int Ks = K / SPLITK;
    int k0base = split * Ks;
    int tid = threadIdx.x, wid = tid >> 5, lane = tid & 31;
    constexpr int WCOLS = BN / WN;
    int wm0 = (wid / WCOLS) * WM;
    int wn0 = (wid % WCOLS) * WN;
    constexpr int MF = WM/16, NF = WN/16;

    wmma::fragment<wmma::accumulator,16,16,16,float> fc[MF][NF];
#pragma unroll
    for (int i = 0; i < MF; i++)
#pragma unroll
        for (int j = 0; j < NF; j++) wmma::fill_fragment(fc[i][j], 0.0f);

    uint32_t asm_base[3] = { smem_u32(AsBase), smem_u32(AsBase + AS_ELEMS),
                             smem_u32(AsBase + 2*AS_ELEMS) };
    uint32_t bsm_base[3] = { smem_u32(BsBase), smem_u32(BsBase + BS_ELEMS),
                             smem_u32(BsBase + 2*BS_ELEMS) };

    auto issue_stage = [&](int s, int k0) {
#pragma unroll
        for (int c = tid; c < BM*4; c += 256) {
            int row = c >> 2, ch = c & 3;
            CP_ASYNC16(asm_base[s] + (row*BKP + ch*8)*2,
                       A + (long long)(bm + row)*lda + k0 + ch*8);
        }
        if (BTRANS == 0) {
#pragma unroll
            for (int c = tid; c < BN*4; c += 256) {
                int row = c >> 2, ch = c & 3;
                CP_ASYNC16(bsm_base[s] + (row*BKP + ch*8)*2,
                           B + (long long)(bn + row)*ldb + k0 + ch*8);
            }
        } else {
#pragma unroll
            for (int c = tid; c < BK*(BN/8); c += 256) {
                int k = c / (BN/8), ch = c % (BN/8);
                CP_ASYNC16(bsm_base[s] + (k*BNP + ch*8)*2,
                           B + (long long)(k0 + k)*ldb + bn + ch*8);
            }
        }
    };

    int KT = Ks / BK;
    issue_stage(0, k0base);
    CP_COMMIT();
    if (KT > 1) issue_stage(1, k0base + BK);
    CP_COMMIT();

    for (int kt = 0; kt < KT; kt++) {
        CP_WAIT1();
        __syncthreads();
        if (kt + 2 < KT) issue_stage((kt + 2) % 3, k0base + (kt + 2) * BK);
        CP_COMMIT();
        bf16* As = AsBase + (kt % 3) * AS_ELEMS;
        bf16* Bs = BsBase + (kt % 3) * BS_ELEMS;
#pragma unroll
        for (int kk = 0; kk < BK; kk += 16) {
            wmma::fragment<wmma::matrix_a,16,16,16,bf16,wmma::row_major> fa[MF];
#pragma unroll
            for (int i = 0; i < MF; i++)
                wmma::load_matrix_sync(fa[i], &As[(wm0 + i*16)*BKP + kk], BKP);
            if (BTRANS == 0) {
#pragma unroll
                for (int j = 0; j < NF; j++) {
                    wmma::fragment<wmma::matrix_b,16,16,16,bf16,wmma::col_major> fb;
                    wmma::load_matrix_sync(fb, &Bs[(wn0 + j*16)*BKP + kk], BKP);
#pragma unroll
                    for (int i = 0; i < MF; i++)
                        wmma::mma_sync(fc[i][j], fa[i], fb, fc[i][j]);
                }
            } else {
#pragma unroll
                for (int j = 0; j < NF; j++) {
                    wmma::fragment<wmma::matrix_b,16,16,16,bf16,wmma::row_major> fb;
                    wmma::load_matrix_sync(fb, &Bs[kk*BNP + wn0 + j*16], BNP);
#pragma unroll
                    for (int i = 0; i < MF; i++)
                        wmma::mma_sync(fc[i][j], fa[i], fb, fc[i][j]);
                }
            }
        }
        __syncthreads();
    }

    float* st = reinterpret_cast<float*>(AsBase) + wid * 256;
#pragma unroll
    for (int i = 0; i < MF; i++) {
#pragma unroll
        for (int j = 0; j < NF; j++) {
            wmma::store_matrix_sync(st, fc[i][j], 16, wmma::mem_row_major);
            __syncwarp();
            int m0 = bm + wm0 + i*16, n0 = bn + wn0 + j*16;
#pragma unroll
            for (int e = 0; e < 8; e++) {
                int idx = e*32 + lane;
                int r = idx >> 4, c = idx & 15;
                float val = st[idx];
                int n = n0 + c;
                if (SPLITK > 1) {
                    if (bias && split == 0) val += bias[(long long)z*sBias + n];
                    atomicAdd((float*)&C[(long long)(m0 + r)*ldc + n], val);
                } else {
                    if (bias) val += bias[(long long)z*sBias + n];
                    if (ACT == 1) val = gelu_exact(val);
                    C[(long long)(m0 + r)*ldc + n] = to_out<OutT>(val);
                }
            }
            __syncwarp();
        }
    }
}

// ---------------- v = einsum('ij,tjd->itd', v_fact, xt_heads) -------------
__global__ void vproj_kernel(const float* __restrict__ xt, const float* __restrict__ vf,
                             float* __restrict__ v) {
    int t = blockIdx.x, h = blockIdx.y, d = threadIdx.x;   // 64 threads
    float acc = 0.f;
#pragma unroll
    for (int j = 0; j < H; j++) acc += vf[h*H + j] * xt[t*D + j*HD + d];
    v[(h*T + t)*HD + d] = acc;
}

// ============================================================================
// Flash attention: CTA = 64 q-rows x head, wmma bf16, fp32 online softmax
// ============================================================================
#define FA_LDB 72
#define FA_LDF 68
__global__ void __launch_bounds__(256) flash_attn(
    const float* __restrict__ qk, const float* __restrict__ v,
    float* __restrict__ y)
{
    extern __shared__ char sm[];
    bf16*  Qs = (bf16*)sm;
    bf16*  Ks = (bf16*)(sm + 9216);
    bf16*  Vs = (bf16*)(sm + 18432);
    bf16*  Pb = (bf16*)(sm + 27648);
    float* Sf = (float*)(sm + 36864);
    float* Ob = (float*)(sm + 54272);
    float* mrow = (float*)(sm + 71680);
    float* lrow = (float*)(sm + 71936);
    float* frow = (float*)(sm + 72192);

    int qt = gridDim.x - 1 - blockIdx.x;
    int h = blockIdx.y;
    int q0 = qt * 64;
    int tid = threadIdx.x, wid = tid >> 5;
    int r = tid >> 2, kq = tid & 3;
    float slope = c_slopes[h];

    {
        const float* qp = qk + (long long)(q0 + r)*(2*D) + h*HD + kq*16;
#pragma unroll
        for (int i = 0; i < 4; i++) {
            float4 x = *(const float4*)(qp + i*4);
            bf16* d = &Qs[r*FA_LDB + kq*16 + i*4];
            d[0] = __float2bfloat16(x.x); d[1] = __float2bfloat16(x.y);
            d[2] = __float2bfloat16(x.z); d[3] = __float2bfloat16(x.w);
        }
    }
#pragma unroll
    for (int i = 0; i < 16; i++) Ob[r*FA_LDF + kq*16 + i] = 0.f;
    if (tid < 64) { mrow[tid] = -INFINITY; lrow[tid] = 0.f; }
    __syncthreads();

    int R = (wid >> 1) * 16, C = (wid & 1) * 32;

    for (int jt = 0; jt <= qt; jt++) {
        int j0 = jt * 64;
        {
            const float* kp = qk + (long long)(j0 + r)*(2*D) + D + h*HD + kq*16;
            const float* vp = v + ((long long)h*T + j0 + r)*HD + kq*16;
#pragma unroll
            for (int i = 0; i < 4; i++) {
                float4 xk = *(const float4*)(kp + i*4);
                bf16* dk = &Ks[r*FA_LDB + kq*16 + i*4];
                dk[0] = __float2bfloat16(xk.x); dk[1] = __float2bfloat16(xk.y);
                dk[2] = __float2bfloat16(xk.z); dk[3] = __float2bfloat16(xk.w);
                float4 xv = *(const float4*)(vp + i*4);
                bf16* dv = &Vs[r*FA_LDB + kq*16 + i*4];
                dv[0] = __float2bfloat16(xv.x); dv[1] = __float2bfloat16(xv.y);
                dv[2] = __float2bfloat16(xv.z); dv[3] = __float2bfloat16(xv.w);
            }
        }
        __syncthreads();

        {
            wmma::fragment<wmma::accumulator,16,16,16,float> sf[2];
            wmma::fill_fragment(sf[0], 0.f);
            wmma::fill_fragment(sf[1], 0.f);
#pragma unroll
            for (int kk = 0; kk < HD; kk += 16) {
                wmma::fragment<wmma::matrix_a,16,16,16,bf16,wmma::row_major> fa;
                wmma::fragment<wmma::matrix_b,16,16,16,bf16,wmma::col_major> fb0, fb1;
                wmma::load_matrix_sync(fa, &Qs[R*FA_LDB + kk], FA_LDB);
                wmma::load_matrix_sync(fb0, &Ks[C*FA_LDB + kk], FA_LDB);
                wmma::load_matrix_sync(fb1, &Ks[(C+16)*FA_LDB + kk], FA_LDB);
                wmma::mma_sync(sf[0], fa, fb0, sf[0]);
                wmma::mma_sync(sf[1], fa, fb1, sf[1]);
            }
            wmma::store_matrix_sync(&Sf[R*FA_LDF + C], sf[0], FA_LDF, wmma::mem_row_major);
            wmma::store_matrix_sync(&Sf[R*FA_LDF + C + 16], sf[1], FA_LDF, wmma::mem_row_major);
        }
        __syncthreads();

        {
            int qi = q0 + r;
            float lmax = -INFINITY;
            float vals[16];
#pragma unroll
            for (int i = 0; i < 16; i++) {
                int j = kq*16 + i;
                int jg = j0 + j;
                float val = (jg <= qi)
                    ? Sf[r*FA_LDF + j]*0.125f + slope*(float)(jg - qi)
                    : -INFINITY;
                vals[i] = val;
                lmax = fmaxf(lmax, val);
            }
            lmax = fmaxf(lmax, __shfl_xor_sync(0xFFFFFFFF, lmax, 1));
            lmax = fmaxf(lmax, __shfl_xor_sync(0xFFFFFFFF, lmax, 2));
            float mold = mrow[r];
            float mnew = fmaxf(mold, lmax);
            float lsum = 0.f;
#pragma unroll
            for (int i = 0; i < 16; i++) {
                float p = __expf(vals[i] - mnew);
                Pb[r*FA_LDB + kq*16 + i] = __float2bfloat16(p);
                lsum += p;
            }
            lsum += __shfl_xor_sync(0xFFFFFFFF, lsum, 1);
            lsum += __shfl_xor_sync(0xFFFFFFFF, lsum, 2);
            if (kq == 0) {
                float f = __expf(mold - mnew);
                frow[r] = f;
                lrow[r] = lrow[r]*f + lsum;
                mrow[r] = mnew;
            }
        }
        __syncthreads();

        {
            float f = frow[r];
#pragma unroll
            for (int i = 0; i < 16; i++) Ob[r*FA_LDF + kq*16 + i] *= f;
        }
        __syncthreads();

        {
            wmma::fragment<wmma::accumulator,16,16,16,float> of[2];
            wmma::load_matrix_sync(of[0], &Ob[R*FA_LDF + C], FA_LDF, wmma::mem_row_major);
            wmma::load_matrix_sync(of[1], &Ob[R*FA_LDF + C + 16], FA_LDF, wmma::mem_row_major);
#pragma unroll
            for (int kk = 0; kk < 64; kk += 16) {
                wmma::fragment<wmma::matrix_a,16,16,16,bf16,wmma::row_major> fa;
                wmma::fragment<wmma::matrix_b,16,16,16,bf16,wmma::row_major> fb0, fb1;
                wmma::load_matrix_sync(fa, &Pb[R*FA_LDB + kk], FA_LDB);
                wmma::load_matrix_sync(fb0, &Vs[kk*FA_LDB + C], FA_LDB);
                wmma::load_matrix_sync(fb1, &Vs[kk*FA_LDB + C + 16], FA_LDB);
                wmma::mma_sync(of[0], fa, fb0, of[0]);
                wmma::mma_sync(of[1], fa, fb1, of[1]);
            }
            wmma::store_matrix_sync(&Ob[R*FA_LDF + C], of[0], FA_LDF, wmma::mem_row_major);
            wmma::store_matrix_sync(&Ob[R*FA_LDF + C + 16], of[1], FA_LDF, wmma::mem_row_major);
        }
        __syncthreads();
    }

    {
        float inv = 1.0f / lrow[r];
        float* yp = y + ((long long)h*T + q0 + r)*HD + kq*16;
#pragma unroll
        for (int i = 0; i < 16; i++) yp[i] = Ob[r*FA_LDF + kq*16 + i] * inv;
    }
}

// ---------------- xt_new = xt + out_fact-lift(y) --------------------------
__global__ void mixout_kernel(const float* __restrict__ xt, const float* __restrict__ of,
                              const float* __restrict__ y, float* __restrict__ xt_new) {
    int t = blockIdx.x, c = threadIdx.x;   // 768 threads
    int i = c >> 6, d = c & 63;
    float acc = xt[t*D + c];
#pragma unroll
    for (int j = 0; j < H; j++) acc += of[i*H + j] * y[((long long)j*T + t)*HD + d];
    xt_new[t*D + c] = acc;
}

// ---------------- per-head LN over 64 (dual fp32 + bf16 output) -----------
__global__ void dln_kernel(const float* __restrict__ p, const float* __restrict__ w,
                           const float* __restrict__ b, float* __restrict__ xhat,
                           bf16* __restrict__ xhat_bf) {
    int row = blockIdx.x;                  // h*T + t
    int h = row >> 10;
    int tid = threadIdx.x;                 // 64
    __shared__ float r[64];
    float x = p[(long long)row*HD + tid];
    r[tid] = x; __syncthreads();
    for (int st = 32; st > 0; st >>= 1) { if (tid < st) r[tid] += r[tid+st]; __syncthreads(); }
    float mu = r[0] / HD;
    __syncthreads();
    float d = x - mu;
    r[tid] = d*d; __syncthreads();
    for (int st = 32; st > 0; st >>= 1) { if (tid < st) r[tid] += r[tid+st]; __syncthreads(); }
    float rs = rsqrtf(r[0]/HD + 1e-5f);
    float val = d * rs * w[h*HD + tid] + b[h*HD + tid];
    xhat[(long long)row*HD + tid] = val;
    xhat_bf[(long long)row*HD + tid] = __float2bfloat16(val);
}

// ---------------- in-place softmax over V=8192 (float4, 256 thr) ----------
__global__ void dsoftmax_kernel(float* __restrict__ dw, bf16* __restrict__ pb) {
    long long row = blockIdx.x;            // rows within one head
    float4* p4 = (float4*)(dw + row * V);
    uint2* pb4 = (uint2*)(pb + row * V);
    int tid = threadIdx.x;                 // 256
    __shared__ float4 sh4[V/4];            // 32 KB
    __shared__ float red[256];
    float m = -INFINITY;
    for (int i = tid; i < V/4; i += 256) {
        float4 x = p4[i]; sh4[i] = x;
        m = fmaxf(m, fmaxf(fmaxf(x.x, x.y), fmaxf(x.z, x.w)));
    }
    red[tid] = m; __syncthreads();
    for (int st = 128; st > 0; st >>= 1) { if (tid < st) red[tid] = fmaxf(red[tid], red[tid+st]); __syncthreads(); }
    m = red[0];
    __syncthreads();
    float s = 0.f;
    for (int i = tid; i < V/4; i += 256) {
        float4 x = sh4[i];
        x.x = __expf(x.x - m); x.y = __expf(x.y - m);
        x.z = __expf(x.z - m); x.w = __expf(x.w - m);
        sh4[i] = x;
        s += (x.x + x.y) + (x.z + x.w);
    }
    red[tid] = s; __syncthreads();
    for (int st = 128; st > 0; st >>= 1) { if (tid < st) red[tid] += red[tid+st]; __syncthreads(); }
    float inv = 1.0f / red[0];
    __syncthreads();
    for (int i = tid; i < V/4; i += 256) {
        float4 x = sh4[i];
        x.x *= inv; x.y *= inv; x.z *= inv; x.w *= inv;
        p4[i] = x;
        __nv_bfloat162 lo = __float22bfloat162_rn(make_float2(x.x, x.y));
        __nv_bfloat162 hi = __float22bfloat162_rn(make_float2(x.z, x.w));
        uint2 o; o.x = *(uint32_t*)&lo; o.y = *(uint32_t*)&hi;
        pb4[i] = o;
    }
}

// ---------------- loss + xe_new -------------------------------------------
__global__ void zero_loss_kernel(float* loss) { *loss = 0.f; }

__global__ void loss_kernel(const float* __restrict__ xhat, const float* __restrict__ recon,
                            float* __restrict__ loss) {
    int row = blockIdx.x;                  // 12288
    int tid = threadIdx.x;                 // 64
    __shared__ float r[64];
    float d = xhat[(long long)row*HD + tid] - recon[(long long)row*HD + tid];
    r[tid] = d*d; __syncthreads();
    for (int st = 32; st > 0; st >>= 1) { if (tid < st) r[tid] += r[tid+st]; __syncthreads(); }
    if (tid == 0) atomicAdd(loss, r[0] * (1.0f / (float)(H*T*HD)));
}

__global__ void xenew_kernel(const float* __restrict__ xe, const float* __restrict__ recon,
                             float* __restrict__ out_xe) {
    int t = blockIdx.x, c = threadIdx.x;   // 768
    int h = c >> 6, e = c & 63;
    out_xe[t*D + c] = xe[t*D + c] + recon[((long long)h*T + t)*HD + e];
}

// ---------------- launch ---------------------------------------------------
extern "C" void kernel_launch(void* const* d_in, const int* in_sizes, int n_in,
                              void* d_out, int out_size) {
    const float* xt      = (const float*)d_in[0];
    const float* xe      = (const float*)d_in[1];
    const float* ln1_w   = (const float*)d_in[2];
    const float* ln1_b   = (const float*)d_in[3];
    const float* qk_w    = (const float*)d_in[4];
    const float* qk_b    = (const float*)d_in[5];
    const float* v_fact  = (const float*)d_in[6];
    const float* out_fact= (const float*)d_in[7];
    const float* ln2_w   = (const float*)d_in[8];
    const float* ln2_b   = (const float*)d_in[9];
    const float* fc_w    = (const float*)d_in[10];
    const float* fc_b    = (const float*)d_in[11];
    const float* proj_w  = (const float*)d_in[12];
    const float* proj_b  = (const float*)d_in[13];
    const float* dln_w   = (const float*)d_in[14];
    const float* dln_b   = (const float*)d_in[15];
    const float* dict_emb= (const float*)d_in[16];

    float* out = (float*)d_out;
    float* out_xt = out;                       // [T,D]
    float* out_xe = out + (size_t)T*D;         // [T,D]
    float* out_dw = out + (size_t)2*T*D;       // [H,T,V]
    float* out_loss = out + (size_t)2*T*D + (size_t)H*T*V; // scalar

    bf16 *xnorm_bf, *qkw_bf, *fcw_bf, *projw_bf, *dict_bf, *x2_bf, *h_bf, *xhat_bf, *probs_bf;
    float *qkbuf, *vbuf, *ybuf, *pbuf, *xhat, *recon;
    cudaGetSymbolAddress((void**)&xnorm_bf, g_xnorm_bf);
    cudaGetSymbolAddress((void**)&qkbuf, g_qk);
    cudaGetSymbolAddress((void**)&qkw_bf, g_qkw_bf);
    cudaGetSymbolAddress((void**)&fcw_bf, g_fcw_bf);
    cudaGetSymbolAddress((void**)&projw_bf, g_projw_bf);
    cudaGetSymbolAddress((void**)&dict_bf, g_dict_bf);
    cudaGetSymbolAddress((void**)&x2_bf, g_x2_bf);
    cudaGetSymbolAddress((void**)&h_bf, g_h_bf);
    cudaGetSymbolAddress((void**)&vbuf,  g_v);
    cudaGetSymbolAddress((void**)&ybuf,  g_y);
    cudaGetSymbolAddress((void**)&pbuf,  g_proj);
    cudaGetSymbolAddress((void**)&xhat,  g_xhat);
    cudaGetSymbolAddress((void**)&xhat_bf, g_xhat_bf);
    cudaGetSymbolAddress((void**)&probs_bf, g_probs_bf);
    cudaGetSymbolAddress((void**)&recon, g_recon);

    const int SM_128_128 = 3 * (128*40 + 128*40) * 2;   // 61440
    const int SM_128_64  = 3 * (128*40 + 64*40) * 2;    // 46080
    const int SM_RECON   = 3 * (128*40 + 32*72) * 2;    // 44544
    const int SM_FA      = 72448;

    cudaFuncSetAttribute((const void*)bgemm<128,64,32,32,0,0,float>,
                         cudaFuncAttributeMaxDynamicSharedMemorySize, SM_128_64);
    cudaFuncSetAttribute((const void*)bgemm<128,128,64,32,0,1,bf16>,
                         cudaFuncAttributeMaxDynamicSharedMemorySize, SM_128_128);
    cudaFuncSetAttribute((const void*)bgemm<128,128,64,32,0,0,float>,
                         cudaFuncAttributeMaxDynamicSharedMemorySize, SM_128_128);
    cudaFuncSetAttribute((const void*)bgemm<128,64,32,32,0,0,float,8>,
                         cudaFuncAttributeMaxDynamicSharedMemorySize, SM_128_64);
    cudaFuncSetAttribute((const void*)bgemm<128,64,32,32,1,0,float,8>,
                         cudaFuncAttributeMaxDynamicSharedMemorySize, SM_RECON);
    cudaFuncSetAttribute((const void*)flash_attn,
                         cudaFuncAttributeMaxDynamicSharedMemorySize, SM_FA);

    // side stream + events (created once on first, non-captured, call)
    static cudaStream_t s1 = nullptr;
    static cudaEvent_t evFork = nullptr, evJoin = nullptr, evDln = nullptr, evDict = nullptr;
    if (!s1) {
        cudaStreamCreateWithFlags(&s1, cudaStreamNonBlocking);
        cudaEventCreateWithFlags(&evFork, cudaEventDisableTiming);
        cudaEventCreateWithFlags(&evJoin, cudaEventDisableTiming);
        cudaEventCreateWithFlags(&evDln, cudaEventDisableTiming);
        cudaEventCreateWithFlags(&evDict, cudaEventDisableTiming);
    }

    // ---- fork: side stream does big weight conversions + zero fills + vproj
    cudaEventRecord(evFork, 0);
    cudaStreamWaitEvent(s1, evFork, 0);
    f2bf_kernel<<<((int)((size_t)NFF*D/8) + 255)/256, 256, 0, s1>>>(
        (const float4*)fc_w, (uint4*)fcw_bf, (int)((size_t)NFF*D/8));
    f2bf_kernel<<<(H*HD*FF/8 + 255)/256, 256, 0, s1>>>(
        (const float4*)proj_w, (uint4*)projw_bf, H*HD*FF/8);
    f2bf_kernel<<<(H*V*HD/8 + 255)/256, 256, 0, s1>>>(
        (const float4*)dict_emb, (uint4*)dict_bf, H*V*HD/8);
    zero_kernel<<<(H*T*HD/4 + 255)/256, 256, 0, s1>>>((float4*)pbuf, H*T*HD/4);
    zero_kernel<<<(H*T*HD/4 + 255)/256, 256, 0, s1>>>((float4*)recon, H*T*HD/4);
    vproj_kernel<<<dim3(T, H), HD, 0, s1>>>(xt, v_fact, vbuf);
    cudaEventRecord(evJoin, s1);

    // ---- main stream: qkw convert -> ln1 -> qk gemm
    f2bf_kernel<<<(2*D*D/8 + 255)/256, 256>>>((const float4*)qk_w, (uint4*)qkw_bf, 2*D*D/8);
    ln768_kernel<<<T, 256>>>(xt, xe, ln1_w, ln1_b, xnorm_bf);
    bgemm<128,64,32,32,0,0,float><<<dim3(2*D/64, T/128, 1), 256, SM_128_64>>>(
        xnorm_bf, D, 0, qkw_bf, D, 0, qk_b, 0, qkbuf, 2*D, 0, D);

    // ---- join before flash (needs vbuf; also orders fcw/projw/dict/zeros)
    cudaStreamWaitEvent(0, evJoin, 0);

    // 4. flash attention
    flash_attn<<<dim3(T/64, H), 256, SM_FA>>>(qkbuf, vbuf, ybuf);
    // 5. xt_new = xt + out_fact-lift(y)   -> d_out
    mixout_kernel<<<T, D>>>(xt, out_fact, ybuf, out_xt);
    // 6. x2 = LN2(xt_new + xe)  (bf16)
    ln768_kernel<<<T, 256>>>(out_xt, xe, ln2_w, ln2_b, x2_bf);
    // 7. h = gelu(x2 @ fc_w^T + fc_b)   [1024, 36864] bf16 (128x128 tiles)
    bgemm<128,128,64,32,0,1,bf16><<<dim3(NFF/128, T/128, 1), 256, SM_128_128>>>(
        x2_bf, D, 0, fcw_bf, D, 0, fc_b, 0, h_bf, NFF, 0, D);
    // 8. proj (batched over heads, split-K=8): [1024,64] per head, K=3072
    bgemm<128,64,32,32,0,0,float,8><<<dim3(8, T/128, H), 256, SM_128_64>>>(
        h_bf, NFF, FF, projw_bf, FF, (long long)HD*FF,
        proj_b, HD, pbuf, HD, (long long)T*HD, FF);
    // 9. per-head LN (fp32 + bf16)
    dln_kernel<<<H*T, HD>>>(pbuf, dln_w, dln_b, xhat, xhat_bf);

    // ---- per-head dict chain, alternating across 2 streams for L2 locality
    //      logits(h) -> softmax(h) -> recon(h), heads interleaved.
    cudaEventRecord(evDln, 0);
    cudaStreamWaitEvent(s1, evDln, 0);
    for (int h = 0; h < H; h++) {
        cudaStream_t st = (h & 1) ? s1 : (cudaStream_t)0;
        const bf16* xh = xhat_bf + (size_t)h*T*HD;
        const bf16* dc = dict_bf + (size_t)h*V*HD;
        float* dw = out_dw + (size_t)h*T*V;
        bf16*  pbh = probs_bf + (size_t)h*T*V;
        float* rec = recon + (size_t)h*T*HD;
        // 10. logits (K=64): [1024, 8192]
        bgemm<128,128,64,32,0,0,float><<<dim3(V/128, T/128, 1), 256, SM_128_128, st>>>(
            xh, HD, 0, dc, HD, 0, nullptr, 0, dw, V, 0, HD);
        // 11. softmax in place + bf16 copy (per-head rows)
        dsoftmax_kernel<<<T, 256, 0, st>>>(dw, pbh);
        // 12. recon = probs @ dict (split-K=8)
        bgemm<128,64,32,32,1,0,float,8><<<dim3(8, T/128, 1), 256, SM_RECON, st>>>(
            pbh, V, 0, dc, HD, 0, nullptr, 0, rec, HD, 0, V);
    }
    cudaEventRecord(evDict, s1);
    cudaStreamWaitEvent(0, evDict, 0);

    // 13/14. loss
    zero_loss_kernel<<<1, 1>>>(out_loss);
    loss_kernel<<<H*T, HD>>>(xhat, recon, out_loss);
    // 15. xe_new
    xenew_kernel<<<T, D>>>(xe, recon, out_xe);
}

// round 16
// speedup vs baseline: 1.6132x; 1.6132x over previous
#include <cuda_runtime.h>
#include <cuda_bf16.h>
#include <mma.h>
#include <math.h>
#include <stdint.h>

using namespace nvcuda;

#define T 1024
#define D 768
#define H 12
#define FF 3072
#define V 8192
#define HD 64
#define NFF (H*FF)   // 36864

typedef __nv_bfloat16 bf16;

// ---------------- scratch (device globals; no allocation allowed) ----------
__device__ bf16  g_xnorm_bf[T*D];
__device__ float g_qk[T*2*D];
__device__ bf16  g_qkw_bf[2*D*D];
__device__ bf16  g_fcw_bf[(size_t)NFF*D];       // 56.6 MB (L2-resident)
__device__ bf16  g_projw_bf[H*HD*FF];
__device__ bf16  g_dict_bf[H*V*HD];
__device__ bf16  g_x2_bf[T*D];
__device__ bf16  g_h_bf[(size_t)T*NFF];         // 75.5 MB
__device__ float g_v[H*T*HD];
__device__ float g_y[H*T*HD];
__device__ float g_proj[H*T*HD];
__device__ float g_xhat[H*T*HD];
__device__ bf16  g_xhat_bf[H*T*HD];
__device__ bf16  g_probs_bf[(size_t)H*T*V];     // 201 MB
__device__ float g_recon[H*T*HD];

__constant__ float c_slopes[H] = {
    0.5f, 0.25f, 0.125f, 0.0625f, 0.03125f, 0.015625f, 0.0078125f, 0.00390625f,
    0.70710678118654752f, 0.5f, 0.35355339059327376f, 0.25f
};

__device__ __forceinline__ float gelu_exact(float x) {
    return 0.5f * x * (1.0f + erff(x * 0.70710678118654752f));
}

__device__ __forceinline__ uint32_t smem_u32(const void* p) {
    return (uint32_t)__cvta_generic_to_shared(p);
}
#define CP_ASYNC16(dst_u32, src) \
    asm volatile("cp.async.cg.shared.global [%0], [%1], 16;\n" :: "r"(dst_u32), "l"(src))
#define CP_COMMIT() asm volatile("cp.async.commit_group;\n")
#define CP_WAIT1()  asm volatile("cp.async.wait_group 1;\n")

template<typename OutT> __device__ __forceinline__ OutT to_out(float v);
template<> __device__ __forceinline__ float to_out<float>(float v) { return v; }
template<> __device__ __forceinline__ bf16  to_out<bf16>(float v)  { return __float2bfloat16(v); }

// ---------------- fp32 -> bf16 bulk convert (8 elems / thread) ------------
__global__ void f2bf_kernel(const float4* __restrict__ in, uint4* __restrict__ out, int n8) {
    int i = blockIdx.x * 256 + threadIdx.x;
    if (i < n8) {
        float4 a = in[2*i], b = in[2*i+1];
        __nv_bfloat162 p0 = __float22bfloat162_rn(make_float2(a.x, a.y));
        __nv_bfloat162 p1 = __float22bfloat162_rn(make_float2(a.z, a.w));
        __nv_bfloat162 p2 = __float22bfloat162_rn(make_float2(b.x, b.y));
        __nv_bfloat162 p3 = __float22bfloat162_rn(make_float2(b.z, b.w));
        uint4 o;
        o.x = *(uint32_t*)&p0; o.y = *(uint32_t*)&p1;
        o.z = *(uint32_t*)&p2; o.w = *(uint32_t*)&p3;
        out[i] = o;
    }
}

// ---------------- zero fp32 buffer ----------------------------------------
__global__ void zero_kernel(float4* __restrict__ p, int n4) {
    int i = blockIdx.x * 256 + threadIdx.x;
    if (i < n4) p[i] = make_float4(0.f, 0.f, 0.f, 0.f);
}

// ---------------- LayerNorm over 768: out_bf = LN(a+b)*w + bb -------------
__global__ void ln768_kernel(const float* __restrict__ a, const float* __restrict__ b,
                             const float* __restrict__ w, const float* __restrict__ bb,
                             bf16* __restrict__ out) {
    int t = blockIdx.x;
    int tid = threadIdx.x;                  // 256
    __shared__ float x[D];
    __shared__ float red[256];
    for (int i = tid; i < D; i += 256) x[i] = a[t*D + i] + b[t*D + i];
    __syncthreads();
    float s = 0.f;
    for (int i = tid; i < D; i += 256) s += x[i];
    red[tid] = s; __syncthreads();
    for (int st = 128; st > 0; st >>= 1) { if (tid < st) red[tid] += red[tid+st]; __syncthreads(); }
    float mu = red[0] / D;
    __syncthreads();
    float v = 0.f;
    for (int i = tid; i < D; i += 256) { float d = x[i] - mu; v += d*d; }
    red[tid] = v; __syncthreads();
    for (int st = 128; st > 0; st >>= 1) { if (tid < st) red[tid] += red[tid+st]; __syncthreads(); }
    float rs = rsqrtf(red[0]/D + 1e-5f);
    __syncthreads();
    for (int i = tid; i < D; i += 256)
        out[t*D + i] = __float2bfloat16((x[i] - mu) * rs * w[i] + bb[i]);
}

// ============================================================================
// bf16 GEMM, 3-stage cp.async pipeline (dynamic smem), fp32 accumulate.
//   BTRANS=0: C = A[M,K] * B[N,K]^T ; BTRANS=1: C = A[M,K] * B[K,N]
//   ACT=1: exact GELU. SPLITK>1: atomicAdd into pre-zeroed fp32 C.
// ============================================================================
template<int BM, int BN, int WM, int WN, int BTRANS, int ACT, typename OutT, int SPLITK = 1>
__global__ void __launch_bounds__(256) bgemm(
    const bf16* __restrict__ A, int lda, long long sA,
    const bf16* __restrict__ B, int ldb, long long sB,
    const float* __restrict__ bias, long long sBias,
    OutT* __restrict__ C, int ldc, long long sC, int K)
{
    constexpr int BK = 32;
    constexpr int BKP = 40;
    constexpr int BNP = BN + 8;
    constexpr int AS_ELEMS = BM * BKP;
    constexpr int BS_ELEMS = BTRANS ? BK * BNP : BN * BKP;
    extern __shared__ char smraw[];
    bf16* AsBase = (bf16*)smraw;
    bf16* BsBase = (bf16*)(smraw + 3 * AS_ELEMS * 2);

    int z = blockIdx.z;
    A += (long long)z * sA; B += (long long)z * sB; C += (long long)z * sC;
    int nTiles = gridDim.x / SPLITK;
    int ntile = blockIdx.x % nTiles;
    int split = blockIdx.x / nTiles;
    int bm = blockIdx.y * BM, bn = ntile * BN;
    int Ks = K / SPLITK;
    int k0base = split * Ks;
    int tid = threadIdx.x, wid = tid >> 5, lane = tid & 31;
    constexpr int WCOLS = BN / WN;
    int wm0 = (wid / WCOLS) * WM;
    int wn0 = (wid % WCOLS) * WN;
    constexpr int MF = WM/16, NF = WN/16;

    wmma::fragment<wmma::accumulator,16,16,16,float> fc[MF][NF];
#pragma unroll
    for (int i = 0; i < MF; i++)
#pragma unroll
        for (int j = 0; j < NF; j++) wmma::fill_fragment(fc[i][j], 0.0f);

    uint32_t asm_base[3] = { smem_u32(AsBase), smem_u32(AsBase + AS_ELEMS),
                             smem_u32(AsBase + 2*AS_ELEMS) };
    uint32_t bsm_base[3] = { smem_u32(BsBase), smem_u32(BsBase + BS_ELEMS),
                             smem_u32(BsBase + 2*BS_ELEMS) };

    auto issue_stage = [&](int s, int k0) {
#pragma unroll
        for (int c = tid; c < BM*4; c += 256) {
            int row = c >> 2, ch = c & 3;
            CP_ASYNC16(asm_base[s] + (row*BKP + ch*8)*2,
                       A + (long long)(bm + row)*lda + k0 + ch*8);
        }
        if (BTRANS == 0) {
#pragma unroll
            for (int c = tid; c < BN*4; c += 256) {
                int row = c >> 2, ch = c & 3;
                CP_ASYNC16(bsm_base[s] + (row*BKP + ch*8)*2,
                           B + (long long)(bn + row)*ldb + k0 + ch*8);
            }
        } else {
#pragma unroll
            for (int c = tid; c < BK*(BN/8); c += 256) {
                int k = c / (BN/8), ch = c % (BN/8);
                CP_ASYNC16(bsm_base[s] + (k*BNP + ch*8)*2,
                           B + (long long)(k0 + k)*ldb + bn + ch*8);
            }
        }
    };

    int KT = Ks / BK;
    issue_stage(0, k0base);
    CP_COMMIT();
    if (KT > 1) issue_stage(1, k0base + BK);
    CP_COMMIT();

    for (int kt = 0; kt < KT; kt++) {
        CP_WAIT1();
        __syncthreads();
        if (kt + 2 < KT) issue_stage((kt + 2) % 3, k0base + (kt + 2) * BK);
        CP_COMMIT();
        bf16* As = AsBase + (kt % 3) * AS_ELEMS;
        bf16* Bs = BsBase + (kt % 3) * BS_ELEMS;
#pragma unroll
        for (int kk = 0; kk < BK; kk += 16) {
            wmma::fragment<wmma::matrix_a,16,16,16,bf16,wmma::row_major> fa[MF];
#pragma unroll
            for (int i = 0; i < MF; i++)
                wmma::load_matrix_sync(fa[i], &As[(wm0 + i*16)*BKP + kk], BKP);
            if (BTRANS == 0) {
#pragma unroll
                for (int j = 0; j < NF; j++) {
                    wmma::fragment<wmma::matrix_b,16,16,16,bf16,wmma::col_major> fb;
                    wmma::load_matrix_sync(fb, &Bs[(wn0 + j*16)*BKP + kk], BKP);
#pragma unroll
                    for (int i = 0; i < MF; i++)
                        wmma::mma_sync(fc[i][j], fa[i], fb, fc[i][j]);
                }
            } else {
#pragma unroll
                for (int j = 0; j < NF; j++) {
                    wmma::fragment<wmma::matrix_b,16,16,16,bf16,wmma::row_major> fb;
                    wmma::load_matrix_sync(fb, &Bs[kk*BNP + wn0 + j*16], BNP);
#pragma unroll
                    for (int i = 0; i < MF; i++)
                        wmma::mma_sync(fc[i][j], fa[i], fb, fc[i][j]);
                }
            }
        }
        __syncthreads();
    }

    float* st = reinterpret_cast<float*>(AsBase) + wid * 256;
#pragma unroll
    for (int i = 0; i < MF; i++) {
#pragma unroll
        for (int j = 0; j < NF; j++) {
            wmma::store_matrix_sync(st, fc[i][j], 16, wmma::mem_row_major);
            __syncwarp();
            int m0 = bm + wm0 + i*16, n0 = bn + wn0 + j*16;
#pragma unroll
            for (int e = 0; e < 8; e++) {
                int idx = e*32 + lane;
                int r = idx >> 4, c = idx & 15;
                float val = st[idx];
                int n = n0 + c;
                if (SPLITK > 1) {
                    if (bias && split == 0) val += bias[(long long)z*sBias + n];
                    atomicAdd((float*)&C[(long long)(m0 + r)*ldc + n], val);
                } else {
                    if (bias) val += bias[(long long)z*sBias + n];
                    if (ACT == 1) val = gelu_exact(val);
                    C[(long long)(m0 + r)*ldc + n] = to_out<OutT>(val);
                }
            }
            __syncwarp();
        }
    }
}

// ---------------- v = einsum('ij,tjd->itd', v_fact, xt_heads) -------------
__global__ void vproj_kernel(const float* __restrict__ xt, const float* __restrict__ vf,
                             float* __restrict__ v) {
    int t = blockIdx.x, h = blockIdx.y, d = threadIdx.x;   // 64 threads
    float acc = 0.f;
#pragma unroll
    for (int j = 0; j < H; j++) acc += vf[h*H + j] * xt[t*D + j*HD + d];
    v[(h*T + t)*HD + d] = acc;
}

// ============================================================================
// Flash attention: CTA = 64 q-rows x head, wmma bf16, fp32 online softmax
// ============================================================================
#define FA_LDB 72
#define FA_LDF 68
__global__ void __launch_bounds__(256) flash_attn(
    const float* __restrict__ qk, const float* __restrict__ v,
    float* __restrict__ y)
{
    extern __shared__ char sm[];
    bf16*  Qs = (bf16*)sm;
    bf16*  Ks = (bf16*)(sm + 9216);
    bf16*  Vs = (bf16*)(sm + 18432);
    bf16*  Pb = (bf16*)(sm + 27648);
    float* Sf = (float*)(sm + 36864);
    float* Ob = (float*)(sm + 54272);
    float* mrow = (float*)(sm + 71680);
    float* lrow = (float*)(sm + 71936);
    float* frow = (float*)(sm + 72192);

    int qt = gridDim.x - 1 - blockIdx.x;
    int h = blockIdx.y;
    int q0 = qt * 64;
    int tid = threadIdx.x, wid = tid >> 5;
    int r = tid >> 2, kq = tid & 3;
    float slope = c_slopes[h];

    {
        const float* qp = qk + (long long)(q0 + r)*(2*D) + h*HD + kq*16;
#pragma unroll
        for (int i = 0; i < 4; i++) {
            float4 x = *(const float4*)(qp + i*4);
            bf16* d = &Qs[r*FA_LDB + kq*16 + i*4];
            d[0] = __float2bfloat16(x.x); d[1] = __float2bfloat16(x.y);
            d[2] = __float2bfloat16(x.z); d[3] = __float2bfloat16(x.w);
        }
    }
#pragma unroll
    for (int i = 0; i < 16; i++) Ob[r*FA_LDF + kq*16 + i] = 0.f;
    if (tid < 64) { mrow[tid] = -INFINITY; lrow[tid] = 0.f; }
    __syncthreads();

    int R = (wid >> 1) * 16, C = (wid & 1) * 32;

    for (int jt = 0; jt <= qt; jt++) {
        int j0 = jt * 64;
        {
            const float* kp = qk + (long long)(j0 + r)*(2*D) + D + h*HD + kq*16;
            const float* vp = v + ((long long)h*T + j0 + r)*HD + kq*16;
#pragma unroll
            for (int i = 0; i < 4; i++) {
                float4 xk = *(const float4*)(kp + i*4);
                bf16* dk = &Ks[r*FA_LDB + kq*16 + i*4];
                dk[0] = __float2bfloat16(xk.x); dk[1] = __float2bfloat16(xk.y);
                dk[2] = __float2bfloat16(xk.z); dk[3] = __float2bfloat16(xk.w);
                float4 xv = *(const float4*)(vp + i*4);
                bf16* dv = &Vs[r*FA_LDB + kq*16 + i*4];
                dv[0] = __float2bfloat16(xv.x); dv[1] = __float2bfloat16(xv.y);
                dv[2] = __float2bfloat16(xv.z); dv[3] = __float2bfloat16(xv.w);
            }
        }
        __syncthreads();

        {
            wmma::fragment<wmma::accumulator,16,16,16,float> sf[2];
            wmma::fill_fragment(sf[0], 0.f);
            wmma::fill_fragment(sf[1], 0.f);
#pragma unroll
            for (int kk = 0; kk < HD; kk += 16) {
                wmma::fragment<wmma::matrix_a,16,16,16,bf16,wmma::row_major> fa;
                wmma::fragment<wmma::matrix_b,16,16,16,bf16,wmma::col_major> fb0, fb1;
                wmma::load_matrix_sync(fa, &Qs[R*FA_LDB + kk], FA_LDB);
                wmma::load_matrix_sync(fb0, &Ks[C*FA_LDB + kk], FA_LDB);
                wmma::load_matrix_sync(fb1, &Ks[(C+16)*FA_LDB + kk], FA_LDB);
                wmma::mma_sync(sf[0], fa, fb0, sf[0]);
                wmma::mma_sync(sf[1], fa, fb1, sf[1]);
            }
            wmma::store_matrix_sync(&Sf[R*FA_LDF + C], sf[0], FA_LDF, wmma::mem_row_major);
            wmma::store_matrix_sync(&Sf[R*FA_LDF + C + 16], sf[1], FA_LDF, wmma::mem_row_major);
        }
        __syncthreads();

        {
            int qi = q0 + r;
            float lmax = -INFINITY;
            float vals[16];
#pragma unroll
            for (int i = 0; i < 16; i++) {
                int j = kq*16 + i;
                int jg = j0 + j;
                float val = (jg <= qi)
                    ? Sf[r*FA_LDF + j]*0.125f + slope*(float)(jg - qi)
                    : -INFINITY;
                vals[i] = val;
                lmax = fmaxf(lmax, val);
            }
            lmax = fmaxf(lmax, __shfl_xor_sync(0xFFFFFFFF, lmax, 1));
            lmax = fmaxf(lmax, __shfl_xor_sync(0xFFFFFFFF, lmax, 2));
            float mold = mrow[r];
            float mnew = fmaxf(mold, lmax);
            float lsum = 0.f;
#pragma unroll
            for (int i = 0; i < 16; i++) {
                float p = __expf(vals[i] - mnew);
                Pb[r*FA_LDB + kq*16 + i] = __float2bfloat16(p);
                lsum += p;
            }
            lsum += __shfl_xor_sync(0xFFFFFFFF, lsum, 1);
            lsum += __shfl_xor_sync(0xFFFFFFFF, lsum, 2);
            if (kq == 0) {
                float f = __expf(mold - mnew);
                frow[r] = f;
                lrow[r] = lrow[r]*f + lsum;
                mrow[r] = mnew;
            }
        }
        __syncthreads();

        {
            float f = frow[r];
#pragma unroll
            for (int i = 0; i < 16; i++) Ob[r*FA_LDF + kq*16 + i] *= f;
        }
        __syncthreads();

        {
            wmma::fragment<wmma::accumulator,16,16,16,float> of[2];
            wmma::load_matrix_sync(of[0], &Ob[R*FA_LDF + C], FA_LDF, wmma::mem_row_major);
            wmma::load_matrix_sync(of[1], &Ob[R*FA_LDF + C + 16], FA_LDF, wmma::mem_row_major);
#pragma unroll
            for (int kk = 0; kk < 64; kk += 16) {
                wmma::fragment<wmma::matrix_a,16,16,16,bf16,wmma::row_major> fa;
                wmma::fragment<wmma::matrix_b,16,16,16,bf16,wmma::row_major> fb0, fb1;
                wmma::load_matrix_sync(fa, &Pb[R*FA_LDB + kk], FA_LDB);
                wmma::load_matrix_sync(fb0, &Vs[kk*FA_LDB + C], FA_LDB);
                wmma::load_matrix_sync(fb1, &Vs[kk*FA_LDB + C + 16], FA_LDB);
                wmma::mma_sync(of[0], fa, fb0, of[0]);
                wmma::mma_sync(of[1], fa, fb1, of[1]);
            }
            wmma::store_matrix_sync(&Ob[R*FA_LDF + C], of[0], FA_LDF, wmma::mem_row_major);
            wmma::store_matrix_sync(&Ob[R*FA_LDF + C + 16], of[1], FA_LDF, wmma::mem_row_major);
        }
        __syncthreads();
    }

    {
        float inv = 1.0f / lrow[r];
        float* yp = y + ((long long)h*T + q0 + r)*HD + kq*16;
#pragma unroll
        for (int i = 0; i < 16; i++) yp[i] = Ob[r*FA_LDF + kq*16 + i] * inv;
    }
}

// ---------------- xt_new = xt + out_fact-lift(y) --------------------------
__global__ void mixout_kernel(const float* __restrict__ xt, const float* __restrict__ of,
                              const float* __restrict__ y, float* __restrict__ xt_new) {
    int t = blockIdx.x, c = threadIdx.x;   // 768 threads
    int i = c >> 6, d = c & 63;
    float acc = xt[t*D + c];
#pragma unroll
    for (int j = 0; j < H; j++) acc += of[i*H + j] * y[((long long)j*T + t)*HD + d];
    xt_new[t*D + c] = acc;
}

// ---------------- per-head LN over 64 (dual fp32 + bf16 output) -----------
__global__ void dln_kernel(const float* __restrict__ p, const float* __restrict__ w,
                           const float* __restrict__ b, float* __restrict__ xhat,
                           bf16* __restrict__ xhat_bf) {
    int row = blockIdx.x;                  // h*T + t
    int h = row >> 10;
    int tid = threadIdx.x;                 // 64
    __shared__ float r[64];
    float x = p[(long long)row*HD + tid];
    r[tid] = x; __syncthreads();
    for (int st = 32; st > 0; st >>= 1) { if (tid < st) r[tid] += r[tid+st]; __syncthreads(); }
    float mu = r[0] / HD;
    __syncthreads();
    float d = x - mu;
    r[tid] = d*d; __syncthreads();
    for (int st = 32; st > 0; st >>= 1) { if (tid < st) r[tid] += r[tid+st]; __syncthreads(); }
    float rs = rsqrtf(r[0]/HD + 1e-5f);
    float val = d * rs * w[h*HD + tid] + b[h*HD + tid];
    xhat[(long long)row*HD + tid] = val;
    xhat_bf[(long long)row*HD + tid] = __float2bfloat16(val);
}

// ---------------- in-place softmax over V=8192 (float4, 256 thr) ----------
__global__ void dsoftmax_kernel(float* __restrict__ dw, bf16* __restrict__ pb) {
    long long row = blockIdx.x;            // 12288 rows
    float4* p4 = (float4*)(dw + row * V);
    uint2* pb4 = (uint2*)(pb + row * V);
    int tid = threadIdx.x;                 // 256
    __shared__ float4 sh4[V/4];            // 32 KB
    __shared__ float red[256];
    float m = -INFINITY;
    for (int i = tid; i < V/4; i += 256) {
        float4 x = p4[i]; sh4[i] = x;
        m = fmaxf(m, fmaxf(fmaxf(x.x, x.y), fmaxf(x.z, x.w)));
    }
    red[tid] = m; __syncthreads();
    for (int st = 128; st > 0; st >>= 1) { if (tid < st) red[tid] = fmaxf(red[tid], red[tid+st]); __syncthreads(); }
    m = red[0];
    __syncthreads();
    float s = 0.f;
    for (int i = tid; i < V/4; i += 256) {
        float4 x = sh4[i];
        x.x = __expf(x.x - m); x.y = __expf(x.y - m);
        x.z = __expf(x.z - m); x.w = __expf(x.w - m);
        sh4[i] = x;
        s += (x.x + x.y) + (x.z + x.w);
    }
    red[tid] = s; __syncthreads();
    for (int st = 128; st > 0; st >>= 1) { if (tid < st) red[tid] += red[tid+st]; __syncthreads(); }
    float inv = 1.0f / red[0];
    __syncthreads();
    for (int i = tid; i < V/4; i += 256) {
        float4 x = sh4[i];
        x.x *= inv; x.y *= inv; x.z *= inv; x.w *= inv;
        p4[i] = x;
        __nv_bfloat162 lo = __float22bfloat162_rn(make_float2(x.x, x.y));
        __nv_bfloat162 hi = __float22bfloat162_rn(make_float2(x.z, x.w));
        uint2 o; o.x = *(uint32_t*)&lo; o.y = *(uint32_t*)&hi;
        pb4[i] = o;
    }
}

// ---------------- fused xe_new + loss -------------------------------------
__global__ void zero_loss_kernel(float* loss) { *loss = 0.f; }

__global__ void xeloss_kernel(const float* __restrict__ xe,
                              const float* __restrict__ recon,
                              const float* __restrict__ xhat,
                              float* __restrict__ out_xe,
                              float* __restrict__ loss) {
    int t = blockIdx.x, c = threadIdx.x;   // 768
    int h = c >> 6, e = c & 63;
    long long idx = ((long long)h*T + t)*HD + e;
    float rec = recon[idx];
    out_xe[t*D + c] = xe[t*D + c] + rec;
    float d = xhat[idx] - rec;
    __shared__ float r[768];
    r[c] = d*d; __syncthreads();
    if (c < 256) r[c] += r[c + 256] + r[c + 512];
    __syncthreads();
    for (int st = 128; st > 0; st >>= 1) { if (c < st) r[c] += r[c+st]; __syncthreads(); }
    if (c == 0) atomicAdd(loss, r[0] * (1.0f / (float)(H*T*HD)));
}

// ---------------- launch ---------------------------------------------------
extern "C" void kernel_launch(void* const* d_in, const int* in_sizes, int n_in,
                              void* d_out, int out_size) {
    const float* xt      = (const float*)d_in[0];
    const float* xe      = (const float*)d_in[1];
    const float* ln1_w   = (const float*)d_in[2];
    const float* ln1_b   = (const float*)d_in[3];
    const float* qk_w    = (const float*)d_in[4];
    const float* qk_b    = (const float*)d_in[5];
    const float* v_fact  = (const float*)d_in[6];
    const float* out_fact= (const float*)d_in[7];
    const float* ln2_w   = (const float*)d_in[8];
    const float* ln2_b   = (const float*)d_in[9];
    const float* fc_w    = (const float*)d_in[10];
    const float* fc_b    = (const float*)d_in[11];
    const float* proj_w  = (const float*)d_in[12];
    const float* proj_b  = (const float*)d_in[13];
    const float* dln_w   = (const float*)d_in[14];
    const float* dln_b   = (const float*)d_in[15];
    const float* dict_emb= (const float*)d_in[16];

    float* out = (float*)d_out;
    float* out_xt = out;                       // [T,D]
    float* out_xe = out + (size_t)T*D;         // [T,D]
    float* out_dw = out + (size_t)2*T*D;       // [H,T,V]
    float* out_loss = out + (size_t)2*T*D + (size_t)H*T*V; // scalar

    bf16 *xnorm_bf, *qkw_bf, *fcw_bf, *projw_bf, *dict_bf, *x2_bf, *h_bf, *xhat_bf, *probs_bf;
    float *qkbuf, *vbuf, *ybuf, *pbuf, *xhat, *recon;
    cudaGetSymbolAddress((void**)&xnorm_bf, g_xnorm_bf);
    cudaGetSymbolAddress((void**)&qkbuf, g_qk);
    cudaGetSymbolAddress((void**)&qkw_bf, g_qkw_bf);
    cudaGetSymbolAddress((void**)&fcw_bf, g_fcw_bf);
    cudaGetSymbolAddress((void**)&projw_bf, g_projw_bf);
    cudaGetSymbolAddress((void**)&dict_bf, g_dict_bf);
    cudaGetSymbolAddress((void**)&x2_bf, g_x2_bf);
    cudaGetSymbolAddress((void**)&h_bf, g_h_bf);
    cudaGetSymbolAddress((void**)&vbuf,  g_v);
    cudaGetSymbolAddress((void**)&ybuf,  g_y);
    cudaGetSymbolAddress((void**)&pbuf,  g_proj);
    cudaGetSymbolAddress((void**)&xhat,  g_xhat);
    cudaGetSymbolAddress((void**)&xhat_bf, g_xhat_bf);
    cudaGetSymbolAddress((void**)&probs_bf, g_probs_bf);
    cudaGetSymbolAddress((void**)&recon, g_recon);

    const int SM_128_128 = 3 * (128*40 + 128*40) * 2;   // 61440
    const int SM_128_64  = 3 * (128*40 + 64*40) * 2;    // 46080
    const int SM_RECON   = 3 * (128*40 + 32*72) * 2;    // 44544
    const int SM_FA      = 72448;

    cudaFuncSetAttribute((const void*)bgemm<128,64,32,32,0,0,float,2>,
                         cudaFuncAttributeMaxDynamicSharedMemorySize, SM_128_64);
    cudaFuncSetAttribute((const void*)bgemm<128,128,64,32,0,1,bf16>,
                         cudaFuncAttributeMaxDynamicSharedMemorySize, SM_128_128);
    cudaFuncSetAttribute((const void*)bgemm<128,128,64,32,0,0,float>,
                         cudaFuncAttributeMaxDynamicSharedMemorySize, SM_128_128);
    cudaFuncSetAttribute((const void*)bgemm<128,64,32,32,0,0,float,8>,
                         cudaFuncAttributeMaxDynamicSharedMemorySize, SM_128_64);
    cudaFuncSetAttribute((const void*)bgemm<128,64,32,32,1,0,float,8>,
                         cudaFuncAttributeMaxDynamicSharedMemorySize, SM_RECON);
    cudaFuncSetAttribute((const void*)flash_attn,
                         cudaFuncAttributeMaxDynamicSharedMemorySize, SM_FA);

    // side stream + events (created once on first, non-captured, call)
    static cudaStream_t s1 = nullptr;
    static cudaEvent_t evFork = nullptr, evJoin = nullptr;
    if (!s1) {
        cudaStreamCreateWithFlags(&s1, cudaStreamNonBlocking);
        cudaEventCreateWithFlags(&evFork, cudaEventDisableTiming);
        cudaEventCreateWithFlags(&evJoin, cudaEventDisableTiming);
    }

    // ---- fork: side stream does big weight conversions + zero fills + vproj
    cudaEventRecord(evFork, 0);
    cudaStreamWaitEvent(s1, evFork, 0);
    f2bf_kernel<<<((int)((size_t)NFF*D/8) + 255)/256, 256, 0, s1>>>(
        (const float4*)fc_w, (uint4*)fcw_bf, (int)((size_t)NFF*D/8));
    f2bf_kernel<<<(H*HD*FF/8 + 255)/256, 256, 0, s1>>>(
        (const float4*)proj_w, (uint4*)projw_bf, H*HD*FF/8);
    f2bf_kernel<<<(H*V*HD/8 + 255)/256, 256, 0, s1>>>(
        (const float4*)dict_emb, (uint4*)dict_bf, H*V*HD/8);
    zero_kernel<<<(H*T*HD/4 + 255)/256, 256, 0, s1>>>((float4*)pbuf, H*T*HD/4);
    zero_kernel<<<(H*T*HD/4 + 255)/256, 256, 0, s1>>>((float4*)recon, H*T*HD/4);
    vproj_kernel<<<dim3(T, H), HD, 0, s1>>>(xt, v_fact, vbuf);
    cudaEventRecord(evJoin, s1);

    // ---- main stream: zero qkbuf (split-K dest) -> qkw convert -> ln1 -> qk
    zero_kernel<<<(T*2*D/4 + 255)/256, 256>>>((float4*)qkbuf, T*2*D/4);
    f2bf_kernel<<<(2*D*D/8 + 255)/256, 256>>>((const float4*)qk_w, (uint4*)qkw_bf, 2*D*D/8);
    ln768_kernel<<<T, 256>>>(xt, xe, ln1_w, ln1_b, xnorm_bf);
    bgemm<128,64,32,32,0,0,float,2><<<dim3((2*D/64)*2, T/128, 1), 256, SM_128_64>>>(
        xnorm_bf, D, 0, qkw_bf, D, 0, qk_b, 0, qkbuf, 2*D, 0, D);

    // ---- join before flash (needs vbuf; also orders fcw/projw/dict/zeros)
    cudaStreamWaitEvent(0, evJoin, 0);

    // 4. flash attention
    flash_attn<<<dim3(T/64, H), 256, SM_FA>>>(qkbuf, vbuf, ybuf);
    // 5. xt_new = xt + out_fact-lift(y)   -> d_out
    mixout_kernel<<<T, D>>>(xt, out_fact, ybuf, out_xt);
    // 6. x2 = LN2(xt_new + xe)  (bf16)
    ln768_kernel<<<T, 256>>>(out_xt, xe, ln2_w, ln2_b, x2_bf);
    // 7. h = gelu(x2 @ fc_w^T + fc_b)   [1024, 36864] bf16 (128x128 tiles)
    bgemm<128,128,64,32,0,1,bf16><<<dim3(NFF/128, T/128, 1), 256, SM_128_128>>>(
        x2_bf, D, 0, fcw_bf, D, 0, fc_b, 0, h_bf, NFF, 0, D);
    // 8. proj (batched over heads, split-K=8): [1024,64] per head, K=3072
    bgemm<128,64,32,32,0,0,float,8><<<dim3(8, T/128, H), 256, SM_128_64>>>(
        h_bf, NFF, FF, projw_bf, FF, (long long)HD*FF,
        proj_b, HD, pbuf, HD, (long long)T*HD, FF);
    // 9. per-head LN (fp32 + bf16)
    dln_kernel<<<H*T, HD>>>(pbuf, dln_w, dln_b, xhat, xhat_bf);
    // 10. dict logits -> out_dw  (batched, K=64)
    bgemm<128,128,64,32,0,0,float><<<dim3(V/128, T/128, H), 256, SM_128_128>>>(
        xhat_bf, HD, (long long)T*HD, dict_bf, HD, (long long)V*HD,
        nullptr, 0, out_dw, V, (long long)T*V, HD);
    // 11. softmax in place + bf16 copy
    dsoftmax_kernel<<<H*T, 256>>>(out_dw, probs_bf);
    // 12. recon = probs @ dict_emb  (batched, split-K=8, B is [K=V, N=HD])
    bgemm<128,64,32,32,1,0,float,8><<<dim3(8, T/128, H), 256, SM_RECON>>>(
        probs_bf, V, (long long)T*V, dict_bf, HD, (long long)V*HD,
        nullptr, 0, recon, HD, (long long)T*HD, V);
    // 13/14/15. loss + xe_new (fused)
    zero_loss_kernel<<<1, 1>>>(out_loss);
    xeloss_kernel<<<T, D>>>(xe, recon, xhat, out_xe, out_loss);
}